// round 4
// baseline (speedup 1.0000x reference)
#include <cuda_runtime.h>

#define NA 300000
#define NT 300000
#define HID 32
#define NH 4
#define E_IN 1000000
#define E_OUT 1000000
#define E_SP 500000
#define E_TOT (E_IN + E_OUT + E_SP)
#define NLAYERS 4

// ---------------- device scratch (no allocs allowed) ----------------
__device__ float g_xa[NA * HID];
__device__ float g_xt[NT * HID];
__device__ float g_ha[NA * HID];
__device__ float g_ht[NT * HID];
__device__ float g_asrc0[NA * NH];
__device__ float g_adst0[NT * NH];
__device__ float g_asrc1[NT * NH];
__device__ float g_adst1[NA * NH];
__device__ float g_asrc2[NT * NH];
__device__ float g_adst2[NT * NH];
__device__ float g_den0[NT * NH];
__device__ float g_den1[NA * NH];
__device__ float g_den2[NT * NH];
__device__ float g_ex0[E_IN * NH];
__device__ float g_ex1[E_OUT * NH];
__device__ float g_ex2[E_SP * NH];
__device__ float g_agg0[NT * HID];
__device__ float g_agg1[NA * HID];
__device__ float g_agg2[NT * HID];
__device__ float g_sacc[2 * 32 * 32];      // padded: lane j at [j*32]
__device__ float g_attn[2];

// ---------------- helpers ----------------
__device__ __forceinline__ float wsum32(float v) {
    #pragma unroll
    for (int o = 16; o > 0; o >>= 1) v += __shfl_xor_sync(0xffffffffu, v, o);
    return v;
}

__device__ __forceinline__ void red_add_v4(float* addr, float4 v) {
    asm volatile("red.global.add.v4.f32 [%0], {%1,%2,%3,%4};"
                 :: "l"(addr), "f"(v.x), "f"(v.y), "f"(v.z), "f"(v.w)
                 : "memory");
}

// ---------------- kernels ----------------

// encoder: warp per node (grid-stride), W staged in shared
__global__ void enc_kernel(const float* __restrict__ x, const float* __restrict__ W,
                           const float* __restrict__ b, float* __restrict__ out,
                           int n, int K) {
    extern __shared__ float Ws[];
    for (int i = threadIdx.x; i < K * 32; i += blockDim.x) Ws[i] = W[i];
    __syncthreads();
    int lane = threadIdx.x & 31;
    int warp = blockIdx.x * (blockDim.x >> 5) + (threadIdx.x >> 5);
    int nw = gridDim.x * (blockDim.x >> 5);
    float bl = b[lane];
    for (int node = warp; node < n; node += nw) {
        const float* xr = x + (size_t)node * K;
        float acc = bl;
        for (int k = 0; k < K; k++) acc = fmaf(xr[k], Ws[k * 32 + lane], acc);
        out[node * 32 + lane] = fmaxf(acc, 0.f);
    }
}

// projection + attention node terms; W cached in registers, persistent warps
template <int NATT>
__global__ void proj_kernel(const float* __restrict__ x, const float* __restrict__ W,
                            const float* __restrict__ b, float* __restrict__ hout, int n,
                            const float* __restrict__ a0, float* __restrict__ o0,
                            const float* __restrict__ a1, float* __restrict__ o1,
                            const float* __restrict__ a2, float* __restrict__ o2,
                            const float* __restrict__ a3, float* __restrict__ o3) {
    int lane = threadIdx.x & 31;
    int warp = blockIdx.x * (blockDim.x >> 5) + (threadIdx.x >> 5);
    int nw = gridDim.x * (blockDim.x >> 5);
    float wreg[32];
    #pragma unroll
    for (int k = 0; k < 32; k++) wreg[k] = W[k * 32 + lane];
    float bl = b[lane];
    float av0 = 0.f, av1 = 0.f, av2 = 0.f, av3 = 0.f;
    if (NATT > 0) av0 = a0[lane];
    if (NATT > 1) av1 = a1[lane];
    if (NATT > 2) av2 = a2[lane];
    if (NATT > 3) av3 = a3[lane];
    int head = lane >> 3;
    for (int node = warp; node < n; node += nw) {
        float xv = x[node * 32 + lane];
        float acc = bl;
        #pragma unroll
        for (int k = 0; k < 32; k++)
            acc = fmaf(__shfl_sync(0xffffffffu, xv, k), wreg[k], acc);
        hout[node * 32 + lane] = acc;
        #define DOT8(av, ov)                                             \
            {                                                            \
                float p = acc * (av);                                    \
                p += __shfl_xor_sync(0xffffffffu, p, 1);                 \
                p += __shfl_xor_sync(0xffffffffu, p, 2);                 \
                p += __shfl_xor_sync(0xffffffffu, p, 4);                 \
                if ((lane & 7) == 0) (ov)[node * 4 + head] = p;          \
            }
        if (NATT > 0) DOT8(av0, o0)
        if (NATT > 1) DOT8(av1, o1)
        if (NATT > 2) DOT8(av2, o2)
        if (NATT > 3) DOT8(av3, o3)
        #undef DOT8
    }
}

// all 3 relations in one launch: ex = exp(leaky_relu(asrc[si]+adst[di])), den += ex
__global__ void pass1_all(
    const int* __restrict__ ei0, const int* __restrict__ ei1, const int* __restrict__ ei2,
    const float* __restrict__ as0, const float* __restrict__ ad0, float* __restrict__ ex0, float* __restrict__ den0,
    const float* __restrict__ as1, const float* __restrict__ ad1, float* __restrict__ ex1, float* __restrict__ den1,
    const float* __restrict__ as2, const float* __restrict__ ad2, float* __restrict__ ex2, float* __restrict__ den2) {
    int t = blockIdx.x * blockDim.x + threadIdx.x;
    const int* ei; const float *as, *ad; float *exb, *den; int e, E;
    if (t < E_IN)             { ei = ei0; as = as0; ad = ad0; exb = ex0; den = den0; e = t;               E = E_IN;  }
    else if (t < E_IN + E_OUT){ ei = ei1; as = as1; ad = ad1; exb = ex1; den = den1; e = t - E_IN;        E = E_OUT; }
    else if (t < E_TOT)       { ei = ei2; as = as2; ad = ad2; exb = ex2; den = den2; e = t - E_IN - E_OUT; E = E_SP; }
    else return;
    int si = __ldg(ei + e);
    int di = __ldg(ei + E + e);
    float4 s = *(const float4*)(as + si * 4);
    float4 d = *(const float4*)(ad + di * 4);
    float4 ex;
    float v;
    v = s.x + d.x; if (v < 0.f) v *= 0.2f; ex.x = __expf(v);
    v = s.y + d.y; if (v < 0.f) v *= 0.2f; ex.y = __expf(v);
    v = s.z + d.z; if (v < 0.f) v *= 0.2f; ex.z = __expf(v);
    v = s.w + d.w; if (v < 0.f) v *= 0.2f; ex.w = __expf(v);
    *(float4*)(exb + e * 4) = ex;
    red_add_v4(den + di * 4, ex);
}

// all 3 relations, 8 threads/edge: agg[di] += ex * hs[si]  (no division here!)
__global__ void pass2_all(
    const int* __restrict__ ei0, const int* __restrict__ ei1, const int* __restrict__ ei2,
    const float* __restrict__ ex0, const float* __restrict__ hs0, float* __restrict__ agg0,
    const float* __restrict__ ex1, const float* __restrict__ hs1, float* __restrict__ agg1,
    const float* __restrict__ ex2, const float* __restrict__ hs2, float* __restrict__ agg2) {
    long long t = (long long)blockIdx.x * blockDim.x + threadIdx.x;
    long long eg = t >> 3;
    int c = (int)(t & 7);
    const int* ei; const float *exb, *hs; float* agg; int e, E;
    if (eg < E_IN)              { ei = ei0; exb = ex0; hs = hs0; agg = agg0; e = (int)eg;                 E = E_IN;  }
    else if (eg < E_IN + E_OUT) { ei = ei1; exb = ex1; hs = hs1; agg = agg1; e = (int)(eg - E_IN);        E = E_OUT; }
    else if (eg < E_TOT)        { ei = ei2; exb = ex2; hs = hs2; agg = agg2; e = (int)(eg - E_IN - E_OUT); E = E_SP; }
    else return;
    int head = c >> 1;
    int si = __ldg(ei + e);
    int di = __ldg(ei + E + e);
    float w = __ldg(exb + e * 4 + head);
    float4 hv = *(const float4*)(hs + si * 32 + c * 4);
    float4 m = make_float4(hv.x * w, hv.y * w, hv.z * w, hv.w * w);
    red_add_v4(agg + di * 32 + c * 4, m);
}

// semantic-attention score partials for BOTH tx relations in one pass
// acc[j*32] += sum_n tanh((relu(agg_raw[n])/den[n]) @ kw + kb)[j]
__global__ void score2_kernel(const float* __restrict__ agg0, const float* __restrict__ den0,
                              const float* __restrict__ agg2, const float* __restrict__ den2,
                              const float* __restrict__ kw, const float* __restrict__ kb,
                              float* __restrict__ acc, int n) {
    int lane = threadIdx.x & 31;
    int warp = blockIdx.x * (blockDim.x >> 5) + (threadIdx.x >> 5);
    int nw = gridDim.x * (blockDim.x >> 5);
    float kwreg[32];
    #pragma unroll
    for (int k = 0; k < 32; k++) kwreg[k] = kw[k * 32 + lane];
    float kbl = kb[lane];
    int hoff = lane >> 3;
    float t0 = 0.f, t2 = 0.f;
    for (int node = warp; node < n; node += nw) {
        float inv0 = 1.f / (den0[node * 4 + hoff] + 1e-16f);
        float inv2 = 1.f / (den2[node * 4 + hoff] + 1e-16f);
        float x0 = fmaxf(agg0[node * 32 + lane], 0.f) * inv0;
        float x2 = fmaxf(agg2[node * 32 + lane], 0.f) * inv2;
        float a0 = kbl, a2 = kbl;
        #pragma unroll
        for (int k = 0; k < 32; k++) {
            float w = kwreg[k];
            a0 = fmaf(__shfl_sync(0xffffffffu, x0, k), w, a0);
            a2 = fmaf(__shfl_sync(0xffffffffu, x2, k), w, a2);
        }
        t0 += tanhf(a0);
        t2 += tanhf(a2);
    }
    __shared__ float s0[32], s2[32];
    if (threadIdx.x < 32) { s0[threadIdx.x] = 0.f; s2[threadIdx.x] = 0.f; }
    __syncthreads();
    atomicAdd(&s0[lane], t0);
    atomicAdd(&s2[lane], t2);
    __syncthreads();
    if (threadIdx.x < 32) {
        atomicAdd(&acc[threadIdx.x * 32], s0[threadIdx.x]);
        atomicAdd(&acc[1024 + threadIdx.x * 32], s2[threadIdx.x]);
    }
}

// softmax over the 2 tx-relation scores
__global__ void score_fin(const float* __restrict__ acc0, const float* __restrict__ acc2,
                          const float* __restrict__ q, float* __restrict__ attn, float invN) {
    int j = threadIdx.x;  // 32 threads
    float s0 = q[j] * acc0[j * 32] * invN;
    float s2 = q[j] * acc2[j * 32] * invN;
    s0 = wsum32(s0);
    s2 = wsum32(s2);
    if (j == 0) {
        float m = fmaxf(s0, s2);
        float e0 = __expf(s0 - m), e2 = __expf(s2 - m);
        float inv = 1.f / (e0 + e2);
        attn[0] = e0 * inv;
        attn[1] = e2 * inv;
    }
}

__global__ void upd_tx_kernel(const float* __restrict__ agg0, const float* __restrict__ den0,
                              const float* __restrict__ agg2, const float* __restrict__ den2,
                              const float* __restrict__ attn, float* __restrict__ xt,
                              const float* __restrict__ g, const float* __restrict__ b, int n) {
    int lane = threadIdx.x & 31;
    int node = blockIdx.x * (blockDim.x >> 5) + (threadIdx.x >> 5);
    if (node >= n) return;
    int hoff = lane >> 3;
    float a0 = attn[0], a2 = attn[1];
    int i = node * 32 + lane;
    float inv0 = 1.f / (den0[node * 4 + hoff] + 1e-16f);
    float inv2 = 1.f / (den2[node * 4 + hoff] + 1e-16f);
    float v = a0 * fmaxf(agg0[i], 0.f) * inv0 + a2 * fmaxf(agg2[i], 0.f) * inv2;
    v = fmaxf(v, 0.f) + xt[i];
    float m = wsum32(v) * (1.f / 32.f);
    float c = v - m;
    float var = wsum32(c * c) * (1.f / 32.f);
    xt[i] = c * rsqrtf(var + 1e-5f) * g[lane] + b[lane];
}

__global__ void upd_addr_kernel(const float* __restrict__ agg1, const float* __restrict__ den1,
                                float* __restrict__ xa,
                                const float* __restrict__ g, const float* __restrict__ b, int n) {
    int lane = threadIdx.x & 31;
    int node = blockIdx.x * (blockDim.x >> 5) + (threadIdx.x >> 5);
    if (node >= n) return;
    int hoff = lane >> 3;
    int i = node * 32 + lane;
    float inv1 = 1.f / (den1[node * 4 + hoff] + 1e-16f);
    float v = fmaxf(agg1[i], 0.f) * inv1 + xa[i];
    float m = wsum32(v) * (1.f / 32.f);
    float c = v - m;
    float var = wsum32(c * c) * (1.f / 32.f);
    xa[i] = c * rsqrtf(var + 1e-5f) * g[lane] + b[lane];
}

__global__ void head_kernel(const float* __restrict__ xa, const float* __restrict__ w,
                            const float* __restrict__ b, float* __restrict__ out, int n) {
    int lane = threadIdx.x & 31;
    int node = blockIdx.x * (blockDim.x >> 5) + (threadIdx.x >> 5);
    if (node >= n) return;
    float v = xa[node * 32 + lane];
    float s0 = wsum32(v * w[lane * 2 + 0]);
    float s1 = wsum32(v * w[lane * 2 + 1]);
    if (lane == 0) {
        out[node * 2 + 0] = s0 + b[0];
        out[node * 2 + 1] = s1 + b[1];
    }
}

// ---------------- launch ----------------
extern "C" void kernel_launch(void* const* d_in, const int* in_sizes, int n_in,
                              void* d_out, int out_size) {
    const float* x_addr  = (const float*)d_in[0];
    const float* x_tx    = (const float*)d_in[1];
    const int*   ei_in   = (const int*)d_in[2];
    const int*   ei_out  = (const int*)d_in[3];
    const int*   ei_sp   = (const int*)d_in[4];
    const float* enc_w_a = (const float*)d_in[5];
    const float* enc_b_a = (const float*)d_in[6];
    const float* enc_w_t = (const float*)d_in[7];
    const float* enc_b_t = (const float*)d_in[8];
    const float* ln_a_g  = (const float*)d_in[9];
    const float* ln_a_b  = (const float*)d_in[10];
    const float* ln_t_g  = (const float*)d_in[11];
    const float* ln_t_b  = (const float*)d_in[12];
    const float* pw_a    = (const float*)d_in[13];
    const float* pb_a    = (const float*)d_in[14];
    const float* pw_t    = (const float*)d_in[15];
    const float* pb_t    = (const float*)d_in[16];
    const float* att_src = (const float*)d_in[17];
    const float* att_dst = (const float*)d_in[18];
    const float* klin_w  = (const float*)d_in[19];
    const float* klin_b  = (const float*)d_in[20];
    const float* qv      = (const float*)d_in[21];
    const float* lin_w   = (const float*)d_in[22];
    const float* lin_b   = (const float*)d_in[23];
    float* out = (float*)d_out;

    float *xa, *xt, *ha, *ht;
    float *asrc0, *adst0, *asrc1, *adst1, *asrc2, *adst2;
    float *den0, *den1, *den2, *ex0, *ex1, *ex2, *agg0, *agg1, *agg2, *sacc, *attn;
    cudaGetSymbolAddress((void**)&xa, g_xa);
    cudaGetSymbolAddress((void**)&xt, g_xt);
    cudaGetSymbolAddress((void**)&ha, g_ha);
    cudaGetSymbolAddress((void**)&ht, g_ht);
    cudaGetSymbolAddress((void**)&asrc0, g_asrc0);
    cudaGetSymbolAddress((void**)&adst0, g_adst0);
    cudaGetSymbolAddress((void**)&asrc1, g_asrc1);
    cudaGetSymbolAddress((void**)&adst1, g_adst1);
    cudaGetSymbolAddress((void**)&asrc2, g_asrc2);
    cudaGetSymbolAddress((void**)&adst2, g_adst2);
    cudaGetSymbolAddress((void**)&den0, g_den0);
    cudaGetSymbolAddress((void**)&den1, g_den1);
    cudaGetSymbolAddress((void**)&den2, g_den2);
    cudaGetSymbolAddress((void**)&ex0, g_ex0);
    cudaGetSymbolAddress((void**)&ex1, g_ex1);
    cudaGetSymbolAddress((void**)&ex2, g_ex2);
    cudaGetSymbolAddress((void**)&agg0, g_agg0);
    cudaGetSymbolAddress((void**)&agg1, g_agg1);
    cudaGetSymbolAddress((void**)&agg2, g_agg2);
    cudaGetSymbolAddress((void**)&sacc, g_sacc);
    cudaGetSymbolAddress((void**)&attn, g_attn);

    const int WPB = 8;
    const int TPB = WPB * 32;        // 256 threads
    dim3 gridA((NA + WPB - 1) / WPB), gridT((NT + WPB - 1) / WPB), blk(TPB);
    const int PGRID = 1184;          // persistent-style grid for proj/score/enc

    // encoders (W in shared)
    enc_kernel<<<PGRID, TPB, 53 * 32 * 4>>>(x_addr, enc_w_a, enc_b_a, xa, NA, 53);
    enc_kernel<<<PGRID, TPB, 6 * 32 * 4>>>(x_tx, enc_w_t, enc_b_t, xt, NT, 6);

    for (int l = 0; l < NLAYERS; l++) {
        const float* PWA = pw_a + l * 32 * 32;
        const float* PBA = pb_a + l * 32;
        const float* PWT = pw_t + l * 32 * 32;
        const float* PBT = pb_t + l * 32;
        const float* AS = att_src + l * 3 * 32;  // [3][32]
        const float* AD = att_dst + l * 3 * 32;
        const float* KW = klin_w + l * 32 * 32;
        const float* KB = klin_b + l * 32;
        const float* Q  = qv + l * 32;

        // projections + attention node terms (register-cached W)
        proj_kernel<2><<<PGRID, blk>>>(xa, PWA, PBA, ha, NA,
                                       AS + 0 * 32, asrc0,   // rel0 src = addr
                                       AD + 1 * 32, adst1,   // rel1 dst = addr
                                       nullptr, nullptr, nullptr, nullptr);
        proj_kernel<4><<<PGRID, blk>>>(xt, PWT, PBT, ht, NT,
                                       AD + 0 * 32, adst0,   // rel0 dst = tx
                                       AS + 1 * 32, asrc1,   // rel1 src = tx
                                       AS + 2 * 32, asrc2,   // rel2 src = tx
                                       AD + 2 * 32, adst2);

        cudaMemsetAsync(den0, 0, (size_t)NT * NH * sizeof(float));
        cudaMemsetAsync(den1, 0, (size_t)NA * NH * sizeof(float));
        cudaMemsetAsync(den2, 0, (size_t)NT * NH * sizeof(float));
        cudaMemsetAsync(agg0, 0, (size_t)NT * HID * sizeof(float));
        cudaMemsetAsync(agg1, 0, (size_t)NA * HID * sizeof(float));
        cudaMemsetAsync(agg2, 0, (size_t)NT * HID * sizeof(float));
        cudaMemsetAsync(sacc, 0, 2 * 32 * 32 * sizeof(float));

        pass1_all<<<(E_TOT + 255) / 256, 256>>>(
            ei_in, ei_out, ei_sp,
            asrc0, adst0, ex0, den0,
            asrc1, adst1, ex1, den1,
            asrc2, adst2, ex2, den2);

        pass2_all<<<(int)(((long long)E_TOT * 8 + 255) / 256), 256>>>(
            ei_in, ei_out, ei_sp,
            ex0, ha, agg0,
            ex1, ht, agg1,
            ex2, ht, agg2);

        // semantic attention over the two tx relations (normalization folded in)
        score2_kernel<<<PGRID, blk>>>(agg0, den0, agg2, den2, KW, KB, sacc, NT);
        score_fin<<<1, 32>>>(sacc, sacc + 1024, Q, attn, 1.0f / (float)NT);

        // residual + layernorm (normalization folded in)
        upd_tx_kernel<<<gridT, blk>>>(agg0, den0, agg2, den2, attn, xt, ln_t_g, ln_t_b, NT);
        upd_addr_kernel<<<gridA, blk>>>(agg1, den1, xa, ln_a_g, ln_a_b, NA);
    }

    head_kernel<<<gridA, blk>>>(xa, lin_w, lin_b, out, NA);
}

// round 5
// speedup vs baseline: 1.2383x; 1.2383x over previous
#include <cuda_runtime.h>

#define NA 300000
#define NT 300000
#define HID 32
#define NH 4
#define E_IN 1000000
#define E_OUT 1000000
#define E_SP 500000
#define E_TOT (E_IN + E_OUT + E_SP)
#define NLAYERS 4
#define SCAN_B 1024

// ---------------- device scratch (no allocs allowed) ----------------
__device__ float g_xa[NA * HID];
__device__ float g_xt[NT * HID];
__device__ float g_ha[NA * HID];
__device__ float g_ht[NT * HID];
__device__ float g_asrc0[NA * NH];
__device__ float g_adst0[NT * NH];
__device__ float g_asrc1[NT * NH];
__device__ float g_adst1[NA * NH];
__device__ float g_asrc2[NT * NH];
__device__ float g_adst2[NT * NH];
__device__ float g_o0[NT * HID];
__device__ float g_o2[NT * HID];
__device__ float g_sacc[2 * 32 * 32];      // padded: lane j at [j*32]
__device__ float g_attn[2];
// CSR scratch
__device__ int g_rp0[NT + 1];
__device__ int g_rp1[NA + 1];
__device__ int g_rp2[NT + 1];
__device__ int g_wcur0[NT];
__device__ int g_wcur1[NA];
__device__ int g_wcur2[NT];
__device__ int g_adj0[E_IN];
__device__ int g_adj1[E_OUT];
__device__ int g_adj2[E_SP];
__device__ int g_bsums0[SCAN_B];
__device__ int g_bsums1[SCAN_B];
__device__ int g_bsums2[SCAN_B];

// ---------------- helpers ----------------
__device__ __forceinline__ float wsum32(float v) {
    #pragma unroll
    for (int o = 16; o > 0; o >>= 1) v += __shfl_xor_sync(0xffffffffu, v, o);
    return v;
}

// ---------------- CSR build ----------------
__global__ void count_all(const int* __restrict__ ei0, const int* __restrict__ ei1,
                          const int* __restrict__ ei2,
                          int* __restrict__ d0, int* __restrict__ d1, int* __restrict__ d2) {
    int t = blockIdx.x * blockDim.x + threadIdx.x;
    if (t < E_IN)                  atomicAdd(&d0[__ldg(ei0 + E_IN + t)], 1);
    else if (t < E_IN + E_OUT)     atomicAdd(&d1[__ldg(ei1 + E_OUT + (t - E_IN))], 1);
    else if (t < E_TOT)            atomicAdd(&d2[__ldg(ei2 + E_SP + (t - E_IN - E_OUT))], 1);
}

__global__ void scan1(int* __restrict__ d, int* __restrict__ bsums, int n) {
    __shared__ int s[SCAN_B];
    int i = blockIdx.x * SCAN_B + threadIdx.x;
    int v = (i < n) ? d[i] : 0;
    s[threadIdx.x] = v;
    __syncthreads();
    for (int o = 1; o < SCAN_B; o <<= 1) {
        int t = (threadIdx.x >= o) ? s[threadIdx.x - o] : 0;
        __syncthreads();
        s[threadIdx.x] += t;
        __syncthreads();
    }
    if (i < n) d[i] = s[threadIdx.x] - v;        // exclusive
    if (threadIdx.x == SCAN_B - 1) bsums[blockIdx.x] = s[SCAN_B - 1];
}

__global__ void scan2(int* __restrict__ bsums, int nb) {
    __shared__ int s[SCAN_B];
    int v = (threadIdx.x < nb) ? bsums[threadIdx.x] : 0;
    s[threadIdx.x] = v;
    __syncthreads();
    for (int o = 1; o < SCAN_B; o <<= 1) {
        int t = (threadIdx.x >= o) ? s[threadIdx.x - o] : 0;
        __syncthreads();
        s[threadIdx.x] += t;
        __syncthreads();
    }
    if (threadIdx.x < nb) bsums[threadIdx.x] = s[threadIdx.x] - v;   // exclusive
}

__global__ void scan3(int* __restrict__ d, const int* __restrict__ bsums, int n) {
    int i = blockIdx.x * SCAN_B + threadIdx.x;
    if (i < n) d[i] += bsums[blockIdx.x];
}

__global__ void set_term(int* r0, int* r1, int* r2) {
    if (threadIdx.x == 0) { r0[NT] = E_IN; r1[NA] = E_OUT; r2[NT] = E_SP; }
}

__global__ void fill_all(const int* __restrict__ ei0, const int* __restrict__ ei1,
                         const int* __restrict__ ei2,
                         const int* __restrict__ r0, const int* __restrict__ r1,
                         const int* __restrict__ r2,
                         int* __restrict__ w0, int* __restrict__ w1, int* __restrict__ w2,
                         int* __restrict__ a0, int* __restrict__ a1, int* __restrict__ a2) {
    int t = blockIdx.x * blockDim.x + threadIdx.x;
    const int* ei; const int* r; int* w; int* adj; int e, E;
    if (t < E_IN)              { ei = ei0; r = r0; w = w0; adj = a0; e = t;                 E = E_IN;  }
    else if (t < E_IN + E_OUT) { ei = ei1; r = r1; w = w1; adj = a1; e = t - E_IN;          E = E_OUT; }
    else if (t < E_TOT)        { ei = ei2; r = r2; w = w2; adj = a2; e = t - E_IN - E_OUT;  E = E_SP;  }
    else return;
    int si = __ldg(ei + e);
    int di = __ldg(ei + E + e);
    int pos = r[di] + atomicAdd(&w[di], 1);
    adj[pos] = si;
}

// ---------------- node kernels ----------------
__global__ void enc_kernel(const float* __restrict__ x, const float* __restrict__ W,
                           const float* __restrict__ b, float* __restrict__ out,
                           int n, int K) {
    extern __shared__ float Ws[];
    for (int i = threadIdx.x; i < K * 32; i += blockDim.x) Ws[i] = W[i];
    __syncthreads();
    int lane = threadIdx.x & 31;
    int warp = blockIdx.x * (blockDim.x >> 5) + (threadIdx.x >> 5);
    int nw = gridDim.x * (blockDim.x >> 5);
    float bl = b[lane];
    for (int node = warp; node < n; node += nw) {
        const float* xr = x + (size_t)node * K;
        float acc = bl;
        for (int k = 0; k < K; k++) acc = fmaf(xr[k], Ws[k * 32 + lane], acc);
        out[node * 32 + lane] = fmaxf(acc, 0.f);
    }
}

template <int NATT>
__global__ void proj_kernel(const float* __restrict__ x, const float* __restrict__ W,
                            const float* __restrict__ b, float* __restrict__ hout, int n,
                            const float* __restrict__ a0, float* __restrict__ o0,
                            const float* __restrict__ a1, float* __restrict__ o1,
                            const float* __restrict__ a2, float* __restrict__ o2,
                            const float* __restrict__ a3, float* __restrict__ o3) {
    int lane = threadIdx.x & 31;
    int warp = blockIdx.x * (blockDim.x >> 5) + (threadIdx.x >> 5);
    int nw = gridDim.x * (blockDim.x >> 5);
    float wreg[32];
    #pragma unroll
    for (int k = 0; k < 32; k++) wreg[k] = W[k * 32 + lane];
    float bl = b[lane];
    float av0 = 0.f, av1 = 0.f, av2 = 0.f, av3 = 0.f;
    if (NATT > 0) av0 = a0[lane];
    if (NATT > 1) av1 = a1[lane];
    if (NATT > 2) av2 = a2[lane];
    if (NATT > 3) av3 = a3[lane];
    int head = lane >> 3;
    for (int node = warp; node < n; node += nw) {
        float xv = x[node * 32 + lane];
        float acc = bl;
        #pragma unroll
        for (int k = 0; k < 32; k++)
            acc = fmaf(__shfl_sync(0xffffffffu, xv, k), wreg[k], acc);
        hout[node * 32 + lane] = acc;
        #define DOT8(av, ov)                                             \
            {                                                            \
                float p = acc * (av);                                    \
                p += __shfl_xor_sync(0xffffffffu, p, 1);                 \
                p += __shfl_xor_sync(0xffffffffu, p, 2);                 \
                p += __shfl_xor_sync(0xffffffffu, p, 4);                 \
                if ((lane & 7) == 0) (ov)[node * 4 + head] = p;          \
            }
        if (NATT > 0) DOT8(av0, o0)
        if (NATT > 1) DOT8(av1, o1)
        if (NATT > 2) DOT8(av2, o2)
        if (NATT > 3) DOT8(av3, o3)
        #undef DOT8
    }
}

// ---------------- fused gather-aggregation ----------------
// warp per tx node: both tx relations + semantic-attention score partials
__global__ void aggT_kernel(const int* __restrict__ rp0, const int* __restrict__ adj0,
                            const int* __restrict__ rp2, const int* __restrict__ adj2,
                            const float* __restrict__ asrc0, const float* __restrict__ adst0,
                            const float* __restrict__ asrc2, const float* __restrict__ adst2,
                            const float* __restrict__ ha, const float* __restrict__ ht,
                            const float* __restrict__ kw, const float* __restrict__ kb,
                            float* __restrict__ o0out, float* __restrict__ o2out,
                            float* __restrict__ sacc, int n) {
    int lane = threadIdx.x & 31;
    int warp = blockIdx.x * (blockDim.x >> 5) + (threadIdx.x >> 5);
    int nw = gridDim.x * (blockDim.x >> 5);
    float kwreg[32];
    #pragma unroll
    for (int k = 0; k < 32; k++) kwreg[k] = kw[k * 32 + lane];
    float kbl = kb[lane];
    int hoff = lane >> 3;
    float t0 = 0.f, t2 = 0.f;

    for (int node = warp; node < n; node += nw) {
        // ---- relation 0 (addr -> tx) ----
        float den0 = 0.f, acc0 = 0.f;
        {
            float ad = __ldg(adst0 + node * 4 + hoff);
            int s = __ldg(rp0 + node), e = __ldg(rp0 + node + 1);
            int si = (s < e) ? __ldg(adj0 + s) : 0;
            for (int i = s; i < e; i++) {
                int si_n = (i + 1 < e) ? __ldg(adj0 + i + 1) : 0;
                float as = __ldg(asrc0 + si * 4 + hoff);
                float hv = __ldg(ha + si * 32 + lane);
                float v = as + ad;
                if (v < 0.f) v *= 0.2f;
                float ex = __expf(v);
                den0 += ex;
                acc0 = fmaf(ex, hv, acc0);
                si = si_n;
            }
        }
        float x0 = fmaxf(acc0 * (1.f / (den0 + 1e-16f)), 0.f);
        // ---- relation 2 (tx -> tx) ----
        float den2 = 0.f, acc2 = 0.f;
        {
            float ad = __ldg(adst2 + node * 4 + hoff);
            int s = __ldg(rp2 + node), e = __ldg(rp2 + node + 1);
            int si = (s < e) ? __ldg(adj2 + s) : 0;
            for (int i = s; i < e; i++) {
                int si_n = (i + 1 < e) ? __ldg(adj2 + i + 1) : 0;
                float as = __ldg(asrc2 + si * 4 + hoff);
                float hv = __ldg(ht + si * 32 + lane);
                float v = as + ad;
                if (v < 0.f) v *= 0.2f;
                float ex = __expf(v);
                den2 += ex;
                acc2 = fmaf(ex, hv, acc2);
                si = si_n;
            }
        }
        float x2 = fmaxf(acc2 * (1.f / (den2 + 1e-16f)), 0.f);

        o0out[node * 32 + lane] = x0;
        o2out[node * 32 + lane] = x2;

        // ---- semantic-attention score partials (klin GEMV + tanh) ----
        float a0 = kbl, a2 = kbl;
        #pragma unroll
        for (int k = 0; k < 32; k++) {
            float w = kwreg[k];
            a0 = fmaf(__shfl_sync(0xffffffffu, x0, k), w, a0);
            a2 = fmaf(__shfl_sync(0xffffffffu, x2, k), w, a2);
        }
        t0 += tanhf(a0);
        t2 += tanhf(a2);
    }
    __shared__ float s0[32], s2[32];
    if (threadIdx.x < 32) { s0[threadIdx.x] = 0.f; s2[threadIdx.x] = 0.f; }
    __syncthreads();
    atomicAdd(&s0[lane], t0);
    atomicAdd(&s2[lane], t2);
    __syncthreads();
    if (threadIdx.x < 32) {
        atomicAdd(&sacc[threadIdx.x * 32], s0[threadIdx.x]);
        atomicAdd(&sacc[1024 + threadIdx.x * 32], s2[threadIdx.x]);
    }
}

// warp per addr node: relation 1 + residual + layernorm fully fused (attn == 1)
__global__ void aggA_kernel(const int* __restrict__ rp1, const int* __restrict__ adj1,
                            const float* __restrict__ asrc1, const float* __restrict__ adst1,
                            const float* __restrict__ ht, float* __restrict__ xa,
                            const float* __restrict__ g, const float* __restrict__ b, int n) {
    int lane = threadIdx.x & 31;
    int warp = blockIdx.x * (blockDim.x >> 5) + (threadIdx.x >> 5);
    int nw = gridDim.x * (blockDim.x >> 5);
    int hoff = lane >> 3;
    float gl = g[lane], bl = b[lane];
    for (int node = warp; node < n; node += nw) {
        float den = 0.f, acc = 0.f;
        float ad = __ldg(adst1 + node * 4 + hoff);
        int s = __ldg(rp1 + node), e = __ldg(rp1 + node + 1);
        int si = (s < e) ? __ldg(adj1 + s) : 0;
        for (int i = s; i < e; i++) {
            int si_n = (i + 1 < e) ? __ldg(adj1 + i + 1) : 0;
            float as = __ldg(asrc1 + si * 4 + hoff);
            float hv = __ldg(ht + si * 32 + lane);
            float v = as + ad;
            if (v < 0.f) v *= 0.2f;
            float ex = __expf(v);
            den += ex;
            acc = fmaf(ex, hv, acc);
            si = si_n;
        }
        float o = fmaxf(acc * (1.f / (den + 1e-16f)), 0.f);
        int idx = node * 32 + lane;
        float v = o + xa[idx];
        float m = wsum32(v) * (1.f / 32.f);
        float c = v - m;
        float var = wsum32(c * c) * (1.f / 32.f);
        xa[idx] = c * rsqrtf(var + 1e-5f) * gl + bl;
    }
}

// softmax over the 2 tx-relation scores
__global__ void score_fin(const float* __restrict__ acc0, const float* __restrict__ acc2,
                          const float* __restrict__ q, float* __restrict__ attn, float invN) {
    int j = threadIdx.x;  // 32 threads
    float s0 = q[j] * acc0[j * 32] * invN;
    float s2 = q[j] * acc2[j * 32] * invN;
    s0 = wsum32(s0);
    s2 = wsum32(s2);
    if (j == 0) {
        float m = fmaxf(s0, s2);
        float e0 = __expf(s0 - m), e2 = __expf(s2 - m);
        float inv = 1.f / (e0 + e2);
        attn[0] = e0 * inv;
        attn[1] = e2 * inv;
    }
}

__global__ void upd_tx_kernel(const float* __restrict__ o0, const float* __restrict__ o2,
                              const float* __restrict__ attn, float* __restrict__ xt,
                              const float* __restrict__ g, const float* __restrict__ b, int n) {
    int lane = threadIdx.x & 31;
    int node = blockIdx.x * (blockDim.x >> 5) + (threadIdx.x >> 5);
    if (node >= n) return;
    float a0 = attn[0], a2 = attn[1];
    int i = node * 32 + lane;
    float v = fmaxf(a0 * o0[i] + a2 * o2[i], 0.f) + xt[i];
    float m = wsum32(v) * (1.f / 32.f);
    float c = v - m;
    float var = wsum32(c * c) * (1.f / 32.f);
    xt[i] = c * rsqrtf(var + 1e-5f) * g[lane] + b[lane];
}

__global__ void head_kernel(const float* __restrict__ xa, const float* __restrict__ w,
                            const float* __restrict__ b, float* __restrict__ out, int n) {
    int lane = threadIdx.x & 31;
    int node = blockIdx.x * (blockDim.x >> 5) + (threadIdx.x >> 5);
    if (node >= n) return;
    float v = xa[node * 32 + lane];
    float s0 = wsum32(v * w[lane * 2 + 0]);
    float s1 = wsum32(v * w[lane * 2 + 1]);
    if (lane == 0) {
        out[node * 2 + 0] = s0 + b[0];
        out[node * 2 + 1] = s1 + b[1];
    }
}

// ---------------- launch ----------------
extern "C" void kernel_launch(void* const* d_in, const int* in_sizes, int n_in,
                              void* d_out, int out_size) {
    const float* x_addr  = (const float*)d_in[0];
    const float* x_tx    = (const float*)d_in[1];
    const int*   ei_in   = (const int*)d_in[2];
    const int*   ei_out  = (const int*)d_in[3];
    const int*   ei_sp   = (const int*)d_in[4];
    const float* enc_w_a = (const float*)d_in[5];
    const float* enc_b_a = (const float*)d_in[6];
    const float* enc_w_t = (const float*)d_in[7];
    const float* enc_b_t = (const float*)d_in[8];
    const float* ln_a_g  = (const float*)d_in[9];
    const float* ln_a_b  = (const float*)d_in[10];
    const float* ln_t_g  = (const float*)d_in[11];
    const float* ln_t_b  = (const float*)d_in[12];
    const float* pw_a    = (const float*)d_in[13];
    const float* pb_a    = (const float*)d_in[14];
    const float* pw_t    = (const float*)d_in[15];
    const float* pb_t    = (const float*)d_in[16];
    const float* att_src = (const float*)d_in[17];
    const float* att_dst = (const float*)d_in[18];
    const float* klin_w  = (const float*)d_in[19];
    const float* klin_b  = (const float*)d_in[20];
    const float* qv      = (const float*)d_in[21];
    const float* lin_w   = (const float*)d_in[22];
    const float* lin_b   = (const float*)d_in[23];
    float* out = (float*)d_out;

    float *xa, *xt, *ha, *ht;
    float *asrc0, *adst0, *asrc1, *adst1, *asrc2, *adst2;
    float *o0, *o2, *sacc, *attn;
    int *rp0, *rp1, *rp2, *wc0, *wc1, *wc2, *adj0, *adj1, *adj2, *bs0, *bs1, *bs2;
    cudaGetSymbolAddress((void**)&xa, g_xa);
    cudaGetSymbolAddress((void**)&xt, g_xt);
    cudaGetSymbolAddress((void**)&ha, g_ha);
    cudaGetSymbolAddress((void**)&ht, g_ht);
    cudaGetSymbolAddress((void**)&asrc0, g_asrc0);
    cudaGetSymbolAddress((void**)&adst0, g_adst0);
    cudaGetSymbolAddress((void**)&asrc1, g_asrc1);
    cudaGetSymbolAddress((void**)&adst1, g_adst1);
    cudaGetSymbolAddress((void**)&asrc2, g_asrc2);
    cudaGetSymbolAddress((void**)&adst2, g_adst2);
    cudaGetSymbolAddress((void**)&o0, g_o0);
    cudaGetSymbolAddress((void**)&o2, g_o2);
    cudaGetSymbolAddress((void**)&sacc, g_sacc);
    cudaGetSymbolAddress((void**)&attn, g_attn);
    cudaGetSymbolAddress((void**)&rp0, g_rp0);
    cudaGetSymbolAddress((void**)&rp1, g_rp1);
    cudaGetSymbolAddress((void**)&rp2, g_rp2);
    cudaGetSymbolAddress((void**)&wc0, g_wcur0);
    cudaGetSymbolAddress((void**)&wc1, g_wcur1);
    cudaGetSymbolAddress((void**)&wc2, g_wcur2);
    cudaGetSymbolAddress((void**)&adj0, g_adj0);
    cudaGetSymbolAddress((void**)&adj1, g_adj1);
    cudaGetSymbolAddress((void**)&adj2, g_adj2);
    cudaGetSymbolAddress((void**)&bs0, g_bsums0);
    cudaGetSymbolAddress((void**)&bs1, g_bsums1);
    cudaGetSymbolAddress((void**)&bs2, g_bsums2);

    const int WPB = 8;
    const int TPB = WPB * 32;        // 256 threads
    dim3 gridA((NA + WPB - 1) / WPB), gridT((NT + WPB - 1) / WPB), blk(TPB);
    const int PGRID = 1184;          // persistent grid

    // ---- CSR build (graph static across layers) ----
    cudaMemsetAsync(rp0, 0, (NT + 1) * sizeof(int));
    cudaMemsetAsync(rp1, 0, (NA + 1) * sizeof(int));
    cudaMemsetAsync(rp2, 0, (NT + 1) * sizeof(int));
    cudaMemsetAsync(wc0, 0, NT * sizeof(int));
    cudaMemsetAsync(wc1, 0, NA * sizeof(int));
    cudaMemsetAsync(wc2, 0, NT * sizeof(int));
    count_all<<<(E_TOT + 255) / 256, 256>>>(ei_in, ei_out, ei_sp, rp0, rp1, rp2);
    int nbT = (NT + SCAN_B - 1) / SCAN_B;
    int nbA = (NA + SCAN_B - 1) / SCAN_B;
    scan1<<<nbT, SCAN_B>>>(rp0, bs0, NT);
    scan1<<<nbA, SCAN_B>>>(rp1, bs1, NA);
    scan1<<<nbT, SCAN_B>>>(rp2, bs2, NT);
    scan2<<<1, SCAN_B>>>(bs0, nbT);
    scan2<<<1, SCAN_B>>>(bs1, nbA);
    scan2<<<1, SCAN_B>>>(bs2, nbT);
    scan3<<<nbT, SCAN_B>>>(rp0, bs0, NT);
    scan3<<<nbA, SCAN_B>>>(rp1, bs1, NA);
    scan3<<<nbT, SCAN_B>>>(rp2, bs2, NT);
    set_term<<<1, 32>>>(rp0, rp1, rp2);
    fill_all<<<(E_TOT + 255) / 256, 256>>>(ei_in, ei_out, ei_sp, rp0, rp1, rp2,
                                           wc0, wc1, wc2, adj0, adj1, adj2);

    // ---- encoders ----
    enc_kernel<<<PGRID, TPB, 53 * 32 * 4>>>(x_addr, enc_w_a, enc_b_a, xa, NA, 53);
    enc_kernel<<<PGRID, TPB, 6 * 32 * 4>>>(x_tx, enc_w_t, enc_b_t, xt, NT, 6);

    for (int l = 0; l < NLAYERS; l++) {
        const float* PWA = pw_a + l * 32 * 32;
        const float* PBA = pb_a + l * 32;
        const float* PWT = pw_t + l * 32 * 32;
        const float* PBT = pb_t + l * 32;
        const float* AS = att_src + l * 3 * 32;  // [3][32]
        const float* AD = att_dst + l * 3 * 32;
        const float* KW = klin_w + l * 32 * 32;
        const float* KB = klin_b + l * 32;
        const float* Q  = qv + l * 32;

        proj_kernel<2><<<PGRID, blk>>>(xa, PWA, PBA, ha, NA,
                                       AS + 0 * 32, asrc0,   // rel0 src = addr
                                       AD + 1 * 32, adst1,   // rel1 dst = addr
                                       nullptr, nullptr, nullptr, nullptr);
        proj_kernel<4><<<PGRID, blk>>>(xt, PWT, PBT, ht, NT,
                                       AD + 0 * 32, adst0,   // rel0 dst = tx
                                       AS + 1 * 32, asrc1,   // rel1 src = tx
                                       AS + 2 * 32, asrc2,   // rel2 src = tx
                                       AD + 2 * 32, adst2);

        cudaMemsetAsync(sacc, 0, 2 * 32 * 32 * sizeof(float));

        aggT_kernel<<<PGRID, blk>>>(rp0, adj0, rp2, adj2,
                                    asrc0, adst0, asrc2, adst2,
                                    ha, ht, KW, KB, o0, o2, sacc, NT);
        aggA_kernel<<<PGRID, blk>>>(rp1, adj1, asrc1, adst1, ht, xa,
                                    ln_a_g, ln_a_b, NA);
        score_fin<<<1, 32>>>(sacc, sacc + 1024, Q, attn, 1.0f / (float)NT);
        upd_tx_kernel<<<gridT, blk>>>(o0, o2, attn, xt, ln_t_g, ln_t_b, NT);
    }

    head_kernel<<<gridA, blk>>>(xa, lin_w, lin_b, out, NA);
}

// round 6
// speedup vs baseline: 1.3369x; 1.0796x over previous
#include <cuda_runtime.h>

#define NA 300000
#define NT 300000
#define HID 32
#define NH 4
#define E_IN 1000000
#define E_OUT 1000000
#define E_SP 500000
#define E_TOT (E_IN + E_OUT + E_SP)
#define NLAYERS 4
#define SCAN_B 1024

// ---------------- device scratch (no allocs allowed) ----------------
__device__ float g_xa[NA * HID];
__device__ float g_xt[NT * HID];
__device__ float g_ha[NA * HID];
__device__ float g_ht[NT * HID];
__device__ float g_asrc0[NA * NH];
__device__ float g_adst0[NT * NH];
__device__ float g_asrc1[NT * NH];
__device__ float g_adst1[NA * NH];
__device__ float g_asrc2[NT * NH];
__device__ float g_adst2[NT * NH];
__device__ float g_o0[NT * HID];
__device__ float g_o2[NT * HID];
__device__ float g_sacc[2 * 32 * 32];      // padded: lane j at [j*32]
__device__ float g_attn[2];
// CSR scratch
__device__ int g_rp0[NT + 1];
__device__ int g_rp1[NA + 1];
__device__ int g_rp2[NT + 1];
__device__ int g_wcur0[NT];
__device__ int g_wcur1[NA];
__device__ int g_wcur2[NT];
__device__ int g_adj0[E_IN];
__device__ int g_adj1[E_OUT];
__device__ int g_adj2[E_SP];
__device__ int g_bsums0[SCAN_B];
__device__ int g_bsums1[SCAN_B];
__device__ int g_bsums2[SCAN_B];

// ---------------- helpers ----------------
__device__ __forceinline__ float wsum32(float v) {
    #pragma unroll
    for (int o = 16; o > 0; o >>= 1) v += __shfl_xor_sync(0xffffffffu, v, o);
    return v;
}

// ---------------- CSR build ----------------
__global__ void count_all(const int* __restrict__ ei0, const int* __restrict__ ei1,
                          const int* __restrict__ ei2,
                          int* __restrict__ d0, int* __restrict__ d1, int* __restrict__ d2) {
    int t = blockIdx.x * blockDim.x + threadIdx.x;
    if (t < E_IN)                  atomicAdd(&d0[__ldg(ei0 + E_IN + t)], 1);
    else if (t < E_IN + E_OUT)     atomicAdd(&d1[__ldg(ei1 + E_OUT + (t - E_IN))], 1);
    else if (t < E_TOT)            atomicAdd(&d2[__ldg(ei2 + E_SP + (t - E_IN - E_OUT))], 1);
}

__global__ void scan1(int* __restrict__ d, int* __restrict__ bsums, int n) {
    __shared__ int s[SCAN_B];
    int i = blockIdx.x * SCAN_B + threadIdx.x;
    int v = (i < n) ? d[i] : 0;
    s[threadIdx.x] = v;
    __syncthreads();
    for (int o = 1; o < SCAN_B; o <<= 1) {
        int t = (threadIdx.x >= o) ? s[threadIdx.x - o] : 0;
        __syncthreads();
        s[threadIdx.x] += t;
        __syncthreads();
    }
    if (i < n) d[i] = s[threadIdx.x] - v;        // exclusive
    if (threadIdx.x == SCAN_B - 1) bsums[blockIdx.x] = s[SCAN_B - 1];
}

__global__ void scan2(int* __restrict__ bsums, int nb) {
    __shared__ int s[SCAN_B];
    int v = (threadIdx.x < nb) ? bsums[threadIdx.x] : 0;
    s[threadIdx.x] = v;
    __syncthreads();
    for (int o = 1; o < SCAN_B; o <<= 1) {
        int t = (threadIdx.x >= o) ? s[threadIdx.x - o] : 0;
        __syncthreads();
        s[threadIdx.x] += t;
        __syncthreads();
    }
    if (threadIdx.x < nb) bsums[threadIdx.x] = s[threadIdx.x] - v;   // exclusive
}

__global__ void scan3(int* __restrict__ d, const int* __restrict__ bsums, int n) {
    int i = blockIdx.x * SCAN_B + threadIdx.x;
    if (i < n) d[i] += bsums[blockIdx.x];
}

__global__ void set_term(int* r0, int* r1, int* r2) {
    if (threadIdx.x == 0) { r0[NT] = E_IN; r1[NA] = E_OUT; r2[NT] = E_SP; }
}

__global__ void fill_all(const int* __restrict__ ei0, const int* __restrict__ ei1,
                         const int* __restrict__ ei2,
                         const int* __restrict__ r0, const int* __restrict__ r1,
                         const int* __restrict__ r2,
                         int* __restrict__ w0, int* __restrict__ w1, int* __restrict__ w2,
                         int* __restrict__ a0, int* __restrict__ a1, int* __restrict__ a2) {
    int t = blockIdx.x * blockDim.x + threadIdx.x;
    const int* ei; const int* r; int* w; int* adj; int e, E;
    if (t < E_IN)              { ei = ei0; r = r0; w = w0; adj = a0; e = t;                 E = E_IN;  }
    else if (t < E_IN + E_OUT) { ei = ei1; r = r1; w = w1; adj = a1; e = t - E_IN;          E = E_OUT; }
    else if (t < E_TOT)        { ei = ei2; r = r2; w = w2; adj = a2; e = t - E_IN - E_OUT;  E = E_SP;  }
    else return;
    int si = __ldg(ei + e);
    int di = __ldg(ei + E + e);
    int pos = r[di] + atomicAdd(&w[di], 1);
    adj[pos] = si;
}

// ---------------- node kernels ----------------
__global__ void enc_kernel(const float* __restrict__ x, const float* __restrict__ W,
                           const float* __restrict__ b, float* __restrict__ out,
                           int n, int K) {
    extern __shared__ float Ws[];
    for (int i = threadIdx.x; i < K * 32; i += blockDim.x) Ws[i] = W[i];
    __syncthreads();
    int lane = threadIdx.x & 31;
    int warp = blockIdx.x * (blockDim.x >> 5) + (threadIdx.x >> 5);
    int nw = gridDim.x * (blockDim.x >> 5);
    float bl = b[lane];
    for (int node = warp; node < n; node += nw) {
        const float* xr = x + (size_t)node * K;
        float acc = bl;
        for (int k = 0; k < K; k++) acc = fmaf(xr[k], Ws[k * 32 + lane], acc);
        out[node * 32 + lane] = fmaxf(acc, 0.f);
    }
}

// tiled projection: block handles tiles of 32 nodes; thread computes 4 outputs
template <int NATT>
__global__ void projT_kernel(const float* __restrict__ x, const float* __restrict__ W,
                             const float* __restrict__ b, float* __restrict__ hout, int n,
                             const float* __restrict__ a0, float* __restrict__ o0,
                             const float* __restrict__ a1, float* __restrict__ o1,
                             const float* __restrict__ a2, float* __restrict__ o2,
                             const float* __restrict__ a3, float* __restrict__ o3) {
    __shared__ float Ws[32 * 32];
    __shared__ float Xs[32 * 33];
    int tid = threadIdx.x;
    for (int i = tid; i < 1024; i += blockDim.x) Ws[i] = W[i];
    int nloc = tid >> 3;          // node within tile (0..31)
    int jq = (tid & 7) * 4;       // first output column of this thread's quad
    int head = (tid & 7) >> 1;    // head covered by this quad-pair
    float4 bq = *(const float4*)(b + jq);
    float4 av0 = make_float4(0,0,0,0), av1 = av0, av2 = av0, av3 = av0;
    if (NATT > 0) av0 = *(const float4*)(a0 + jq);
    if (NATT > 1) av1 = *(const float4*)(a1 + jq);
    if (NATT > 2) av2 = *(const float4*)(a2 + jq);
    if (NATT > 3) av3 = *(const float4*)(a3 + jq);
    __syncthreads();
    int ntiles = (n + 31) >> 5;
    for (int tile = blockIdx.x; tile < ntiles; tile += gridDim.x) {
        int node = tile * 32 + nloc;
        bool valid = node < n;
        float4 xq = valid ? *(const float4*)(x + (size_t)node * 32 + jq)
                          : make_float4(0.f, 0.f, 0.f, 0.f);
        Xs[nloc * 33 + jq + 0] = xq.x;
        Xs[nloc * 33 + jq + 1] = xq.y;
        Xs[nloc * 33 + jq + 2] = xq.z;
        Xs[nloc * 33 + jq + 3] = xq.w;
        __syncthreads();
        float4 acc = bq;
        #pragma unroll
        for (int k = 0; k < 32; k++) {
            float xk = Xs[nloc * 33 + k];
            float4 wk = *(const float4*)(Ws + k * 32 + jq);
            acc.x = fmaf(xk, wk.x, acc.x);
            acc.y = fmaf(xk, wk.y, acc.y);
            acc.z = fmaf(xk, wk.z, acc.z);
            acc.w = fmaf(xk, wk.w, acc.w);
        }
        if (valid) *(float4*)(hout + (size_t)node * 32 + jq) = acc;
        #define DOTQ(av, ov) { \
            float p = acc.x*(av).x + acc.y*(av).y + acc.z*(av).z + acc.w*(av).w; \
            p += __shfl_xor_sync(0xffffffffu, p, 1); \
            if (valid && ((tid & 1) == 0)) (ov)[node * 4 + head] = p; }
        if (NATT > 0) DOTQ(av0, o0)
        if (NATT > 1) DOTQ(av1, o1)
        if (NATT > 2) DOTQ(av2, o2)
        if (NATT > 3) DOTQ(av3, o3)
        #undef DOTQ
        __syncthreads();
    }
}

// ---------------- fused gather-aggregation (both node types, one launch) ----------------
__device__ __forceinline__ float gather_rel(const int* __restrict__ rp,
                                            const int* __restrict__ adj,
                                            const float* __restrict__ asrc,
                                            const float* __restrict__ adst,
                                            const float* __restrict__ h,
                                            int node, int lane, int hoff) {
    float ad = __ldg(adst + node * 4 + hoff);
    int s = __ldg(rp + node), e = __ldg(rp + node + 1);
    float den = 0.f, acc = 0.f;
    int i = s;
    for (; i + 2 <= e; i += 2) {
        int siA = __ldg(adj + i);
        int siB = __ldg(adj + i + 1);
        float asA = __ldg(asrc + siA * 4 + hoff);
        float asB = __ldg(asrc + siB * 4 + hoff);
        float hA = __ldg(h + (size_t)siA * 32 + lane);
        float hB = __ldg(h + (size_t)siB * 32 + lane);
        float vA = asA + ad; if (vA < 0.f) vA *= 0.2f;
        float vB = asB + ad; if (vB < 0.f) vB *= 0.2f;
        float eA = __expf(vA), eB = __expf(vB);
        den += eA + eB;
        acc = fmaf(eA, hA, fmaf(eB, hB, acc));
    }
    if (i < e) {
        int si = __ldg(adj + i);
        float as = __ldg(asrc + si * 4 + hoff);
        float hv = __ldg(h + (size_t)si * 32 + lane);
        float v = as + ad; if (v < 0.f) v *= 0.2f;
        float ex = __expf(v);
        den += ex;
        acc = fmaf(ex, hv, acc);
    }
    return fmaxf(acc * (1.f / (den + 1e-16f)), 0.f);
}

__global__ void agg_kernel(const int* __restrict__ rp0, const int* __restrict__ adj0,
                           const int* __restrict__ rp2, const int* __restrict__ adj2,
                           const int* __restrict__ rp1, const int* __restrict__ adj1,
                           const float* __restrict__ asrc0, const float* __restrict__ adst0,
                           const float* __restrict__ asrc2, const float* __restrict__ adst2,
                           const float* __restrict__ asrc1, const float* __restrict__ adst1,
                           const float* __restrict__ ha, const float* __restrict__ ht,
                           float* __restrict__ o0out, float* __restrict__ o2out,
                           float* __restrict__ xa,
                           const float* __restrict__ lng, const float* __restrict__ lnb) {
    int lane = threadIdx.x & 31;
    int warp = blockIdx.x * (blockDim.x >> 5) + (threadIdx.x >> 5);
    int nw = gridDim.x * (blockDim.x >> 5);
    int hoff = lane >> 3;
    float gl = lng[lane], bl = lnb[lane];
    for (int idx = warp; idx < NT + NA; idx += nw) {
        if (idx < NT) {
            int node = idx;
            float x0 = gather_rel(rp0, adj0, asrc0, adst0, ha, node, lane, hoff);
            float x2 = gather_rel(rp2, adj2, asrc2, adst2, ht, node, lane, hoff);
            o0out[(size_t)node * 32 + lane] = x0;
            o2out[(size_t)node * 32 + lane] = x2;
        } else {
            int node = idx - NT;
            float o = gather_rel(rp1, adj1, asrc1, adst1, ht, node, lane, hoff);
            int i = node * 32 + lane;
            float v = o + xa[i];        // relation-group softmax weight is exactly 1
            float m = wsum32(v) * (1.f / 32.f);
            float c = v - m;
            float var = wsum32(c * c) * (1.f / 32.f);
            xa[i] = c * rsqrtf(var + 1e-5f) * gl + bl;
        }
    }
}

// tiled semantic-attention score for both tx relations
__global__ void scoreT_kernel(const float* __restrict__ o0, const float* __restrict__ o2,
                              const float* __restrict__ kw, const float* __restrict__ kb,
                              float* __restrict__ sacc, int n) {
    __shared__ float Ws[32 * 32];
    __shared__ float X0[32 * 33];
    __shared__ float X2[32 * 33];
    __shared__ float s0[32], s2[32];
    int tid = threadIdx.x;
    for (int i = tid; i < 1024; i += blockDim.x) Ws[i] = kw[i];
    int nloc = tid >> 3;
    int jq = (tid & 7) * 4;
    float4 kbq = *(const float4*)(kb + jq);
    float4 t0 = make_float4(0,0,0,0), t2 = make_float4(0,0,0,0);
    __syncthreads();
    int ntiles = (n + 31) >> 5;
    for (int tile = blockIdx.x; tile < ntiles; tile += gridDim.x) {
        int node = tile * 32 + nloc;
        bool valid = node < n;
        float4 q0 = valid ? *(const float4*)(o0 + (size_t)node * 32 + jq) : make_float4(0,0,0,0);
        float4 q2 = valid ? *(const float4*)(o2 + (size_t)node * 32 + jq) : make_float4(0,0,0,0);
        X0[nloc*33+jq+0]=q0.x; X0[nloc*33+jq+1]=q0.y; X0[nloc*33+jq+2]=q0.z; X0[nloc*33+jq+3]=q0.w;
        X2[nloc*33+jq+0]=q2.x; X2[nloc*33+jq+1]=q2.y; X2[nloc*33+jq+2]=q2.z; X2[nloc*33+jq+3]=q2.w;
        __syncthreads();
        float4 a0 = kbq, a2 = kbq;
        #pragma unroll
        for (int k = 0; k < 32; k++) {
            float x0k = X0[nloc * 33 + k];
            float x2k = X2[nloc * 33 + k];
            float4 wk = *(const float4*)(Ws + k * 32 + jq);
            a0.x = fmaf(x0k, wk.x, a0.x); a0.y = fmaf(x0k, wk.y, a0.y);
            a0.z = fmaf(x0k, wk.z, a0.z); a0.w = fmaf(x0k, wk.w, a0.w);
            a2.x = fmaf(x2k, wk.x, a2.x); a2.y = fmaf(x2k, wk.y, a2.y);
            a2.z = fmaf(x2k, wk.z, a2.z); a2.w = fmaf(x2k, wk.w, a2.w);
        }
        if (valid) {
            t0.x += tanhf(a0.x); t0.y += tanhf(a0.y); t0.z += tanhf(a0.z); t0.w += tanhf(a0.w);
            t2.x += tanhf(a2.x); t2.y += tanhf(a2.y); t2.z += tanhf(a2.z); t2.w += tanhf(a2.w);
        }
        __syncthreads();
    }
    if (tid < 32) { s0[tid] = 0.f; s2[tid] = 0.f; }
    __syncthreads();
    atomicAdd(&s0[jq+0], t0.x); atomicAdd(&s0[jq+1], t0.y);
    atomicAdd(&s0[jq+2], t0.z); atomicAdd(&s0[jq+3], t0.w);
    atomicAdd(&s2[jq+0], t2.x); atomicAdd(&s2[jq+1], t2.y);
    atomicAdd(&s2[jq+2], t2.z); atomicAdd(&s2[jq+3], t2.w);
    __syncthreads();
    if (tid < 32) {
        atomicAdd(&sacc[tid * 32], s0[tid]);
        atomicAdd(&sacc[1024 + tid * 32], s2[tid]);
    }
}

// softmax over the 2 tx-relation scores
__global__ void score_fin(const float* __restrict__ acc0, const float* __restrict__ acc2,
                          const float* __restrict__ q, float* __restrict__ attn, float invN) {
    int j = threadIdx.x;  // 32 threads
    float s0 = q[j] * acc0[j * 32] * invN;
    float s2 = q[j] * acc2[j * 32] * invN;
    s0 = wsum32(s0);
    s2 = wsum32(s2);
    if (j == 0) {
        float m = fmaxf(s0, s2);
        float e0 = __expf(s0 - m), e2 = __expf(s2 - m);
        float inv = 1.f / (e0 + e2);
        attn[0] = e0 * inv;
        attn[1] = e2 * inv;
    }
}

__global__ void upd_tx_kernel(const float* __restrict__ o0, const float* __restrict__ o2,
                              const float* __restrict__ attn, float* __restrict__ xt,
                              const float* __restrict__ g, const float* __restrict__ b, int n) {
    int lane = threadIdx.x & 31;
    int node = blockIdx.x * (blockDim.x >> 5) + (threadIdx.x >> 5);
    if (node >= n) return;
    float a0 = attn[0], a2 = attn[1];
    int i = node * 32 + lane;
    float v = fmaxf(a0 * o0[i] + a2 * o2[i], 0.f) + xt[i];
    float m = wsum32(v) * (1.f / 32.f);
    float c = v - m;
    float var = wsum32(c * c) * (1.f / 32.f);
    xt[i] = c * rsqrtf(var + 1e-5f) * g[lane] + b[lane];
}

__global__ void head_kernel(const float* __restrict__ xa, const float* __restrict__ w,
                            const float* __restrict__ b, float* __restrict__ out, int n) {
    int lane = threadIdx.x & 31;
    int node = blockIdx.x * (blockDim.x >> 5) + (threadIdx.x >> 5);
    if (node >= n) return;
    float v = xa[node * 32 + lane];
    float s0 = wsum32(v * w[lane * 2 + 0]);
    float s1 = wsum32(v * w[lane * 2 + 1]);
    if (lane == 0) {
        out[node * 2 + 0] = s0 + b[0];
        out[node * 2 + 1] = s1 + b[1];
    }
}

// ---------------- launch ----------------
extern "C" void kernel_launch(void* const* d_in, const int* in_sizes, int n_in,
                              void* d_out, int out_size) {
    const float* x_addr  = (const float*)d_in[0];
    const float* x_tx    = (const float*)d_in[1];
    const int*   ei_in   = (const int*)d_in[2];
    const int*   ei_out  = (const int*)d_in[3];
    const int*   ei_sp   = (const int*)d_in[4];
    const float* enc_w_a = (const float*)d_in[5];
    const float* enc_b_a = (const float*)d_in[6];
    const float* enc_w_t = (const float*)d_in[7];
    const float* enc_b_t = (const float*)d_in[8];
    const float* ln_a_g  = (const float*)d_in[9];
    const float* ln_a_b  = (const float*)d_in[10];
    const float* ln_t_g  = (const float*)d_in[11];
    const float* ln_t_b  = (const float*)d_in[12];
    const float* pw_a    = (const float*)d_in[13];
    const float* pb_a    = (const float*)d_in[14];
    const float* pw_t    = (const float*)d_in[15];
    const float* pb_t    = (const float*)d_in[16];
    const float* att_src = (const float*)d_in[17];
    const float* att_dst = (const float*)d_in[18];
    const float* klin_w  = (const float*)d_in[19];
    const float* klin_b  = (const float*)d_in[20];
    const float* qv      = (const float*)d_in[21];
    const float* lin_w   = (const float*)d_in[22];
    const float* lin_b   = (const float*)d_in[23];
    float* out = (float*)d_out;

    float *xa, *xt, *ha, *ht;
    float *asrc0, *adst0, *asrc1, *adst1, *asrc2, *adst2;
    float *o0, *o2, *sacc, *attn;
    int *rp0, *rp1, *rp2, *wc0, *wc1, *wc2, *adj0, *adj1, *adj2, *bs0, *bs1, *bs2;
    cudaGetSymbolAddress((void**)&xa, g_xa);
    cudaGetSymbolAddress((void**)&xt, g_xt);
    cudaGetSymbolAddress((void**)&ha, g_ha);
    cudaGetSymbolAddress((void**)&ht, g_ht);
    cudaGetSymbolAddress((void**)&asrc0, g_asrc0);
    cudaGetSymbolAddress((void**)&adst0, g_adst0);
    cudaGetSymbolAddress((void**)&asrc1, g_asrc1);
    cudaGetSymbolAddress((void**)&adst1, g_adst1);
    cudaGetSymbolAddress((void**)&asrc2, g_asrc2);
    cudaGetSymbolAddress((void**)&adst2, g_adst2);
    cudaGetSymbolAddress((void**)&o0, g_o0);
    cudaGetSymbolAddress((void**)&o2, g_o2);
    cudaGetSymbolAddress((void**)&sacc, g_sacc);
    cudaGetSymbolAddress((void**)&attn, g_attn);
    cudaGetSymbolAddress((void**)&rp0, g_rp0);
    cudaGetSymbolAddress((void**)&rp1, g_rp1);
    cudaGetSymbolAddress((void**)&rp2, g_rp2);
    cudaGetSymbolAddress((void**)&wc0, g_wcur0);
    cudaGetSymbolAddress((void**)&wc1, g_wcur1);
    cudaGetSymbolAddress((void**)&wc2, g_wcur2);
    cudaGetSymbolAddress((void**)&adj0, g_adj0);
    cudaGetSymbolAddress((void**)&adj1, g_adj1);
    cudaGetSymbolAddress((void**)&adj2, g_adj2);
    cudaGetSymbolAddress((void**)&bs0, g_bsums0);
    cudaGetSymbolAddress((void**)&bs1, g_bsums1);
    cudaGetSymbolAddress((void**)&bs2, g_bsums2);

    const int WPB = 8;
    const int TPB = WPB * 32;        // 256 threads
    dim3 gridA((NA + WPB - 1) / WPB), gridT((NT + WPB - 1) / WPB), blk(TPB);
    const int PGRID = 1184;          // persistent grid (agg)
    const int TGRID = 1480;          // tiled-GEMM grid (proj/score)

    // ---- CSR build (graph static across layers) ----
    cudaMemsetAsync(rp0, 0, (NT + 1) * sizeof(int));
    cudaMemsetAsync(rp1, 0, (NA + 1) * sizeof(int));
    cudaMemsetAsync(rp2, 0, (NT + 1) * sizeof(int));
    cudaMemsetAsync(wc0, 0, NT * sizeof(int));
    cudaMemsetAsync(wc1, 0, NA * sizeof(int));
    cudaMemsetAsync(wc2, 0, NT * sizeof(int));
    count_all<<<(E_TOT + 255) / 256, 256>>>(ei_in, ei_out, ei_sp, rp0, rp1, rp2);
    int nbT = (NT + SCAN_B - 1) / SCAN_B;
    int nbA = (NA + SCAN_B - 1) / SCAN_B;
    scan1<<<nbT, SCAN_B>>>(rp0, bs0, NT);
    scan1<<<nbA, SCAN_B>>>(rp1, bs1, NA);
    scan1<<<nbT, SCAN_B>>>(rp2, bs2, NT);
    scan2<<<1, SCAN_B>>>(bs0, nbT);
    scan2<<<1, SCAN_B>>>(bs1, nbA);
    scan2<<<1, SCAN_B>>>(bs2, nbT);
    scan3<<<nbT, SCAN_B>>>(rp0, bs0, NT);
    scan3<<<nbA, SCAN_B>>>(rp1, bs1, NA);
    scan3<<<nbT, SCAN_B>>>(rp2, bs2, NT);
    set_term<<<1, 32>>>(rp0, rp1, rp2);
    fill_all<<<(E_TOT + 255) / 256, 256>>>(ei_in, ei_out, ei_sp, rp0, rp1, rp2,
                                           wc0, wc1, wc2, adj0, adj1, adj2);

    // ---- encoders ----
    enc_kernel<<<TGRID, TPB, 53 * 32 * 4>>>(x_addr, enc_w_a, enc_b_a, xa, NA, 53);
    enc_kernel<<<TGRID, TPB, 6 * 32 * 4>>>(x_tx, enc_w_t, enc_b_t, xt, NT, 6);

    for (int l = 0; l < NLAYERS; l++) {
        const float* PWA = pw_a + l * 32 * 32;
        const float* PBA = pb_a + l * 32;
        const float* PWT = pw_t + l * 32 * 32;
        const float* PBT = pb_t + l * 32;
        const float* AS = att_src + l * 3 * 32;  // [3][32]
        const float* AD = att_dst + l * 3 * 32;
        const float* KW = klin_w + l * 32 * 32;
        const float* KB = klin_b + l * 32;
        const float* Q  = qv + l * 32;

        projT_kernel<2><<<TGRID, blk>>>(xa, PWA, PBA, ha, NA,
                                        AS + 0 * 32, asrc0,   // rel0 src = addr
                                        AD + 1 * 32, adst1,   // rel1 dst = addr
                                        nullptr, nullptr, nullptr, nullptr);
        projT_kernel<4><<<TGRID, blk>>>(xt, PWT, PBT, ht, NT,
                                        AD + 0 * 32, adst0,   // rel0 dst = tx
                                        AS + 1 * 32, asrc1,   // rel1 src = tx
                                        AS + 2 * 32, asrc2,   // rel2 src = tx
                                        AD + 2 * 32, adst2);

        cudaMemsetAsync(sacc, 0, 2 * 32 * 32 * sizeof(float));

        agg_kernel<<<PGRID, blk>>>(rp0, adj0, rp2, adj2, rp1, adj1,
                                   asrc0, adst0, asrc2, adst2, asrc1, adst1,
                                   ha, ht, o0, o2, xa, ln_a_g, ln_a_b);
        scoreT_kernel<<<TGRID, blk>>>(o0, o2, KW, KB, sacc, NT);
        score_fin<<<1, 32>>>(sacc, sacc + 1024, Q, attn, 1.0f / (float)NT);
        upd_tx_kernel<<<gridT, blk>>>(o0, o2, attn, xt, ln_t_g, ln_t_b, NT);
    }

    head_kernel<<<gridA, blk>>>(xa, lin_w, lin_b, out, NA);
}